// round 6
// baseline (speedup 1.0000x reference)
#include <cuda_runtime.h>
#include <cstdint>
#include <math.h>

// Problem constants
#define B_  32
#define T_  1536
#define C_  768
#define G_  2
#define VG_ 160
#define M_TOTAL (B_*T_)       // 49152
#define N1 (G_*VG_)           // 320
#define N2 C_                 // 768
#define TEMP_ 2.0f

// 63MB scratch for logits (allocation-free rule: __device__ global)
__device__ float g_logits[(size_t)M_TOTAL * N1];

// ---------------- GEMM: C = A(MxK) @ B(KxN) (+bias), single-pass TF32 ----------------
// 3-stage cp.async pipeline, 128x64x32 CTA tile, 8 warps of 32x32.
#define BM 128
#define BN 64
#define BK 32
#define PITCH_A 36   // floats; 144B row, 16B-aligned, conflict-free frag reads
#define PITCH_B 72   // floats; 288B row, 16B-aligned, conflict-free frag reads
#define ASZ (BM * PITCH_A)   // floats per A stage (4608)
#define BSZ (BK * PITCH_B)   // floats per B stage (2304)
#define NSTAGE 3
#define SMEM_BYTES (NSTAGE * (ASZ + BSZ) * 4)   // 82944

__device__ __forceinline__ uint32_t f2tf32(float a) {
    uint32_t u;
    asm("cvt.rna.tf32.f32 %0, %1;" : "=r"(u) : "f"(a));
    return u;
}

__device__ __forceinline__ void mma_m16n8k8(float c[4],
    uint32_t a0, uint32_t a1, uint32_t a2, uint32_t a3,
    uint32_t b0, uint32_t b1)
{
    asm volatile(
        "mma.sync.aligned.m16n8k8.row.col.f32.tf32.tf32.f32 "
        "{%0,%1,%2,%3}, {%4,%5,%6,%7}, {%8,%9}, {%0,%1,%2,%3};"
        : "+f"(c[0]), "+f"(c[1]), "+f"(c[2]), "+f"(c[3])
        : "r"(a0), "r"(a1), "r"(a2), "r"(a3), "r"(b0), "r"(b1));
}

__device__ __forceinline__ void cp16(uint32_t dst_smem, const void* src) {
    asm volatile("cp.async.cg.shared.global [%0], [%1], 16;" :: "r"(dst_smem), "l"(src));
}
__device__ __forceinline__ void cp_commit() {
    asm volatile("cp.async.commit_group;");
}
__device__ __forceinline__ void cp_wait1() {
    asm volatile("cp.async.wait_group 1;");
}

template<int KD, int ND, bool HAS_BIAS>
__global__ __launch_bounds__(256, 2)
void gemm_tf32_pipe(const float* __restrict__ A, const float* __restrict__ Bg,
                    const float* __restrict__ bias, float* __restrict__ Cg)
{
    extern __shared__ float sm[];
    float* smA = sm;                       // NSTAGE * ASZ
    float* smB = sm + NSTAGE * ASZ;        // NSTAGE * BSZ
    uint32_t smA_u32, smB_u32;
    {
        uint32_t base;
        asm("{ .reg .u64 t; cvta.to.shared.u64 t, %1; cvt.u32.u64 %0, t; }"
            : "=r"(base) : "l"(sm));
        smA_u32 = base;
        smB_u32 = base + NSTAGE * ASZ * 4;
    }

    const int tid  = threadIdx.x;
    const int warp = tid >> 5, lane = tid & 31;
    const int wm = warp >> 1, wn = warp & 1;        // 4x2 warps -> 32x32 warp tile
    const int m0 = blockIdx.y * BM, n0 = blockIdx.x * BN;
    const int gid = lane >> 2, tig = lane & 3;

    // Per-thread load coordinates (constant across tiles)
    const int ar = tid >> 3;          // rows tid/8 .. +: 4 chunks of 256 threads cover 128 rows x 8 float4
    // A: lin = tid + i*256 -> r = lin>>3, c4 = lin&7
    // B: lin = tid + i*256 -> kr = lin>>4, n4 = lin&15
    (void)ar;

    float acc[2][4][4];
    #pragma unroll
    for (int mt = 0; mt < 2; mt++)
        #pragma unroll
        for (int nt = 0; nt < 4; nt++)
            #pragma unroll
            for (int r = 0; r < 4; r++) acc[mt][nt][r] = 0.0f;

    auto load_stage = [&](int stage, int k0) {
        // A tile: 128x32 floats = 1024 float4; 4 per thread
        #pragma unroll
        for (int i = 0; i < 4; i++) {
            int lin = tid + i * 256;
            int r = lin >> 3, c4 = lin & 7;
            const float* src = A + (size_t)(m0 + r) * KD + k0 + c4 * 4;
            uint32_t dst = smA_u32 + (uint32_t)(stage * ASZ + r * PITCH_A + c4 * 4) * 4u;
            cp16(dst, src);
        }
        // B tile: 32x64 floats = 512 float4; 2 per thread
        #pragma unroll
        for (int i = 0; i < 2; i++) {
            int lin = tid + i * 256;
            int kr = lin >> 4, n4 = lin & 15;
            const float* src = Bg + (size_t)(k0 + kr) * ND + n0 + n4 * 4;
            uint32_t dst = smB_u32 + (uint32_t)(stage * BSZ + kr * PITCH_B + n4 * 4) * 4u;
            cp16(dst, src);
        }
    };

    constexpr int NIT = KD / BK;
    load_stage(0, 0);        cp_commit();
    load_stage(1, BK);       cp_commit();

    #pragma unroll 1
    for (int it = 0; it < NIT; ++it) {
        cp_wait1();                 // stage it%NSTAGE landed (this thread)
        __syncthreads();            // ... and everyone else's

        // Prefetch stage (it+2)%3 — that buffer was consumed in iteration it-1,
        // and all threads passed the barrier above after computing it-1.
        int kpre = (it + 2) * BK;
        if (kpre < KD) load_stage((it + 2) % NSTAGE, kpre);
        cp_commit();                // always one group per iteration (possibly empty)

        const float* As = smA + (it % NSTAGE) * ASZ;
        const float* Bs = smB + (it % NSTAGE) * BSZ;

        #pragma unroll
        for (int ks = 0; ks < BK; ks += 8) {
            uint32_t af[2][4];
            #pragma unroll
            for (int mt = 0; mt < 2; mt++) {
                int mb = wm * 32 + mt * 16;
                af[mt][0] = f2tf32(As[(mb + gid    ) * PITCH_A + ks + tig    ]);
                af[mt][1] = f2tf32(As[(mb + gid + 8) * PITCH_A + ks + tig    ]);
                af[mt][2] = f2tf32(As[(mb + gid    ) * PITCH_A + ks + tig + 4]);
                af[mt][3] = f2tf32(As[(mb + gid + 8) * PITCH_A + ks + tig + 4]);
            }
            #pragma unroll
            for (int nt = 0; nt < 4; nt++) {
                int nb = wn * 32 + nt * 8 + gid;
                uint32_t b0 = f2tf32(Bs[(ks + tig    ) * PITCH_B + nb]);
                uint32_t b1 = f2tf32(Bs[(ks + tig + 4) * PITCH_B + nb]);
                #pragma unroll
                for (int mt = 0; mt < 2; mt++)
                    mma_m16n8k8(acc[mt][nt], af[mt][0], af[mt][1], af[mt][2], af[mt][3], b0, b1);
            }
        }
    }

    // Epilogue (float2 stores; col0 even -> 8B aligned)
    #pragma unroll
    for (int mt = 0; mt < 2; mt++) {
        #pragma unroll
        for (int nt = 0; nt < 4; nt++) {
            int row0 = m0 + wm * 32 + mt * 16 + gid;
            int col0 = n0 + wn * 32 + nt * 8 + tig * 2;
            float2 v01 = make_float2(acc[mt][nt][0], acc[mt][nt][1]);
            float2 v23 = make_float2(acc[mt][nt][2], acc[mt][nt][3]);
            if (HAS_BIAS) {
                float bv0 = bias[col0], bv1 = bias[col0 + 1];
                v01.x += bv0; v01.y += bv1;
                v23.x += bv0; v23.y += bv1;
            }
            *(float2*)(Cg + (size_t)(row0    ) * ND + col0) = v01;
            *(float2*)(Cg + (size_t)(row0 + 8) * ND + col0) = v23;
        }
    }
}

// -------- Softmax + argmax (+ exact rescue for narrow top-2 gaps) --------
// One warp per (bt, g) row of 160.
#define GAP_THRESH  0.01f   // trigger rescue if top1-top2 below this
#define CAND_WINDOW 0.02f   // candidates within this of approx top1

__global__ void softmax_argmax_kernel(const float* __restrict__ gumbel,
                                      const float* __restrict__ x,
                                      const float* __restrict__ W,
                                      const float* __restrict__ bias,
                                      float* __restrict__ probs_out,
                                      float* __restrict__ codes_out)
{
    const int task = blockIdx.x * 8 + (threadIdx.x >> 5);   // 98304 tasks
    const int lane = threadIdx.x & 31;
    const int row = task >> 1, g = task & 1;

    const float* lp = g_logits + (size_t)row * N1 + g * VG_;
    const float* gp = gumbel   + (size_t)row * N1 + g * VG_;

    float z[5];
    float best = -INFINITY, second = -INFINITY;
    int bidx = 0;
    #pragma unroll
    for (int j = 0; j < 5; j++) {
        int v = lane + j * 32;
        z[j] = lp[v] + gp[v];
        if (z[j] > best) { second = best; best = z[j]; bidx = v; }
        else if (z[j] > second) { second = z[j]; }
    }
    // warp (best, second, bidx) pair-merge reduction, first-occurrence tie-break
    #pragma unroll
    for (int o = 16; o > 0; o >>= 1) {
        float ov = __shfl_xor_sync(0xffffffffu, best,   o);
        float os = __shfl_xor_sync(0xffffffffu, second, o);
        int   oi = __shfl_xor_sync(0xffffffffu, bidx,   o);
        if (ov > best || (ov == best && oi < bidx)) {
            second = fmaxf(best, os);
            best = ov; bidx = oi;
        } else {
            second = fmaxf(second, ov);
        }
    }

    // Rescue: exact (fp64) recompute of near-top candidates to pin the argmax.
    if (best - second < GAP_THRESH) {
        double nbest = -1e300;
        int nidx = 0;
        #pragma unroll
        for (int j = 0; j < 5; j++) {
            unsigned m = __ballot_sync(0xffffffffu, z[j] > best - CAND_WINDOW);
            while (m) {
                int l = __ffs(m) - 1; m &= m - 1;
                int v = l + j * 32;
                int col = g * VG_ + v;
                double part = 0.0;
                const float* xr = x + (size_t)row * C_;
                for (int k = lane; k < C_; k += 32)
                    part += (double)xr[k] * (double)W[(size_t)k * N1 + col];
                #pragma unroll
                for (int o = 16; o > 0; o >>= 1)
                    part += __shfl_xor_sync(0xffffffffu, part, o);
                double ze = part + (double)bias[col] + (double)gp[v];
                if (ze > nbest) { nbest = ze; nidx = v; }  // v strictly ascending -> first max kept
            }
        }
        bidx = nidx;
    }

    const float inv_t = 1.0f / TEMP_;
    float e[5];
    float s = 0.0f;
    #pragma unroll
    for (int j = 0; j < 5; j++) { e[j] = __expf((z[j] - best) * inv_t); s += e[j]; }
    #pragma unroll
    for (int o = 16; o > 0; o >>= 1) s += __shfl_xor_sync(0xffffffffu, s, o);
    float inv_s = 1.0f / s;

    float* po = probs_out + (size_t)row * N1 + g * VG_;
    #pragma unroll
    for (int j = 0; j < 5; j++) po[lane + j * 32] = e[j] * inv_s;

    if (lane == 0) codes_out[task] = (float)bidx;
}

// ---------------- launch ----------------
extern "C" void kernel_launch(void* const* d_in, const int* in_sizes, int n_in,
                              void* d_out, int out_size)
{
    const float* x      = (const float*)d_in[0];  // (B,T,C)
    const float* gumbel = (const float*)d_in[1];  // (B,T,G,Vg)
    const float* W      = (const float*)d_in[2];  // (C, G*Vg)
    const float* bias   = (const float*)d_in[3];  // (G*Vg,)
    const float* cb     = (const float*)d_in[4];  // (G,Vg,C) -> (320,768)

    float* out   = (float*)d_out;
    float* quant = out;                                      // M*C
    float* codes = out + (size_t)M_TOTAL * C_;               // M*G
    float* probs = codes + (size_t)M_TOTAL * G_;             // M*N1

    float* logits_ptr = nullptr;
    cudaGetSymbolAddress((void**)&logits_ptr, g_logits);

    // Allow 83KB dynamic smem (idempotent host-side attribute; not a stream op)
    static bool attr_done = false;
    if (!attr_done) {
        cudaFuncSetAttribute(gemm_tf32_pipe<C_, N1, true>,
                             cudaFuncAttributeMaxDynamicSharedMemorySize, SMEM_BYTES);
        cudaFuncSetAttribute(gemm_tf32_pipe<N1, N2, false>,
                             cudaFuncAttributeMaxDynamicSharedMemorySize, SMEM_BYTES);
        attr_done = true;
    }

    // GEMM1: logits = x @ W + b   (M x 768) @ (768 x 320)
    {
        dim3 grid(N1 / BN, M_TOTAL / BM);   // (5, 384)
        gemm_tf32_pipe<C_, N1, true><<<grid, 256, SMEM_BYTES>>>(x, W, bias, logits_ptr);
    }
    // Softmax + argmax (+rescue) + probs
    {
        softmax_argmax_kernel<<<(M_TOTAL * G_) / 8, 256>>>(gumbel, x, W, bias, probs, codes);
    }
    // GEMM2: quantized = probs @ codebook   (M x 320) @ (320 x 768)
    {
        dim3 grid(N2 / BN, M_TOTAL / BM);   // (12, 384)
        gemm_tf32_pipe<N1, N2, false><<<grid, 256, SMEM_BYTES>>>(probs, cb, nullptr, quant);
    }
}

// round 11
// speedup vs baseline: 2.4541x; 2.4541x over previous
#include <cuda_runtime.h>
#include <cuda_fp16.h>
#include <cstdint>
#include <math.h>

// Problem constants
#define B_  32
#define T_  1536
#define C_  768
#define G_  2
#define VG_ 160
#define M_TOTAL (B_*T_)       // 49152
#define N1 (G_*VG_)           // 320
#define N2 C_                 // 768
#define TEMP_ 2.0f

// GEMM tiling: BM=128, BN=64, BK=64 (fp16), 8 warps of 32x32
#define BK 64
#define P32 36                // b32 pitch per row: 32 data + 4 pad (conflict-free frags)
#define SA (128*P32)          // A stage, b32 units (4608)
#define SB (64*P32)           // B stage, b32 units (2304)
#define SS (SA+SB)            // 6912
#define SMEM_G (2*SS*4)       // 55296 bytes

// ---- device scratch (allocation-free rule) ----
__device__ float   g_logits [(size_t)M_TOTAL * N1];
__device__ __half  g_probs16[(size_t)M_TOTAL * N1];
__device__ __half  g_Wt16   [(size_t)N1 * C_];   // [n][k]
__device__ __half  g_cbt16  [(size_t)C_ * N1];   // [c][v]

__device__ __forceinline__ void mma_f16(float c[4],
    uint32_t a0, uint32_t a1, uint32_t a2, uint32_t a3,
    uint32_t b0, uint32_t b1)
{
    asm volatile(
        "mma.sync.aligned.m16n8k16.row.col.f32.f16.f16.f32 "
        "{%0,%1,%2,%3}, {%4,%5,%6,%7}, {%8,%9}, {%0,%1,%2,%3};"
        : "+f"(c[0]), "+f"(c[1]), "+f"(c[2]), "+f"(c[3])
        : "r"(a0), "r"(a1), "r"(a2), "r"(a3), "r"(b0), "r"(b1));
}

// D[M,N] = A[m][k] * B[n][k]^T ; A fp32 (converted inline) or fp16; B fp16 [n][k].
template<int KD, int ND, int NIT, bool HAS_BIAS, bool A_F16>
__global__ __launch_bounds__(256, 2)
void gemm_f16_pipe(const float* __restrict__ A32, const __half* __restrict__ A16,
                   const __half* __restrict__ Bg,
                   const float* __restrict__ bias, float* __restrict__ Out)
{
    extern __shared__ uint32_t sm32[];
    uint32_t* aS[2] = { sm32,       sm32 + SS };
    uint32_t* bS[2] = { sm32 + SA,  sm32 + SS + SA };

    const int tid  = threadIdx.x;
    const int warp = tid >> 5, lane = tid & 31;
    const int wm = warp >> 1, wn = warp & 1;     // 4x2 warps -> 32x32 warp tiles
    const int m0 = blockIdx.y * 128, n0 = blockIdx.x * 64;
    const int g = lane >> 2, t = lane & 3;

    float acc[2][4][4];
    #pragma unroll
    for (int mt = 0; mt < 2; mt++)
        #pragma unroll
        for (int nt = 0; nt < 4; nt++)
            #pragma unroll
            for (int r = 0; r < 4; r++) acc[mt][nt][r] = 0.0f;

    // staging registers
    float4 avf[8];
    uint4  avh[4];
    uint4  bv[2];

    auto ldg = [&](int k0) {
        if (A_F16) {
            #pragma unroll
            for (int i = 0; i < 4; i++) {
                int idx = tid + i * 256, r = idx >> 3, ch = idx & 7;
                avh[i] = *(const uint4*)(A16 + (size_t)(m0 + r) * KD + k0 + ch * 8);
            }
        } else {
            #pragma unroll
            for (int i = 0; i < 8; i++) {
                int idx = tid + i * 256, r = idx >> 4, c4 = idx & 15;
                avf[i] = *(const float4*)(A32 + (size_t)(m0 + r) * KD + k0 + c4 * 4);
            }
        }
        #pragma unroll
        for (int i = 0; i < 2; i++) {
            int idx = tid + i * 256, r = idx >> 3, ch = idx & 7;
            bv[i] = *(const uint4*)(Bg + (size_t)(n0 + r) * KD + k0 + ch * 8);
        }
    };

    auto sts = [&](int s) {
        uint32_t* aD = aS[s];
        uint32_t* bD = bS[s];
        if (A_F16) {
            #pragma unroll
            for (int i = 0; i < 4; i++) {
                int idx = tid + i * 256, r = idx >> 3, ch = idx & 7;
                *(uint4*)(aD + r * P32 + ch * 4) = avh[i];
            }
        } else {
            #pragma unroll
            for (int i = 0; i < 8; i++) {
                int idx = tid + i * 256, r = idx >> 4, c4 = idx & 15;
                __half2 h01 = __floats2half2_rn(avf[i].x, avf[i].y);  // x -> low half (even k)
                __half2 h23 = __floats2half2_rn(avf[i].z, avf[i].w);
                *(uint2*)(aD + r * P32 + c4 * 2) =
                    make_uint2(*(uint32_t*)&h01, *(uint32_t*)&h23);
            }
        }
        #pragma unroll
        for (int i = 0; i < 2; i++) {
            int idx = tid + i * 256, r = idx >> 3, ch = idx & 7;
            *(uint4*)(bD + r * P32 + ch * 4) = bv[i];
        }
    };

    ldg(0);
    #pragma unroll 1
    for (int it = 0; it < NIT; ++it) {
        sts(it & 1);
        if (it + 1 < NIT) ldg((it + 1) * BK);
        __syncthreads();

        const uint32_t* aB = aS[it & 1];
        const uint32_t* bB = bS[it & 1];
        #pragma unroll
        for (int ks = 0; ks < 4; ks++) {
            const int kc = ks * 8;
            uint32_t a[2][4];
            #pragma unroll
            for (int mt = 0; mt < 2; mt++) {
                int r0 = wm * 32 + mt * 16 + g;
                a[mt][0] = aB[(r0    ) * P32 + kc + t    ];
                a[mt][1] = aB[(r0 + 8) * P32 + kc + t    ];
                a[mt][2] = aB[(r0    ) * P32 + kc + t + 4];
                a[mt][3] = aB[(r0 + 8) * P32 + kc + t + 4];
            }
            #pragma unroll
            for (int nt = 0; nt < 4; nt++) {
                int rb = wn * 32 + nt * 8 + g;
                uint32_t b0 = bB[rb * P32 + kc + t    ];
                uint32_t b1 = bB[rb * P32 + kc + t + 4];
                mma_f16(acc[0][nt], a[0][0], a[0][1], a[0][2], a[0][3], b0, b1);
                mma_f16(acc[1][nt], a[1][0], a[1][1], a[1][2], a[1][3], b0, b1);
            }
        }
    }

    // Epilogue (float2 stores)
    #pragma unroll
    for (int mt = 0; mt < 2; mt++) {
        #pragma unroll
        for (int nt = 0; nt < 4; nt++) {
            int row0 = m0 + wm * 32 + mt * 16 + g;
            int col0 = n0 + wn * 32 + nt * 8 + t * 2;
            float2 v01 = make_float2(acc[mt][nt][0], acc[mt][nt][1]);
            float2 v23 = make_float2(acc[mt][nt][2], acc[mt][nt][3]);
            if (HAS_BIAS) {
                float bv0 = bias[col0], bv1 = bias[col0 + 1];
                v01.x += bv0; v01.y += bv1;
                v23.x += bv0; v23.y += bv1;
            }
            *(float2*)(Out + (size_t)(row0    ) * ND + col0) = v01;
            *(float2*)(Out + (size_t)(row0 + 8) * ND + col0) = v23;
        }
    }
}

// ---------------- prep: transpose + fp16 convert of W and codebook ----------------
__global__ void prep_Wt(const float* __restrict__ W) {
    int i = blockIdx.x * 256 + threadIdx.x;          // over N1*C_
    if (i >= N1 * C_) return;
    int n = i / C_, k = i % C_;
    g_Wt16[i] = __float2half_rn(W[(size_t)k * N1 + n]);
}
__global__ void prep_cbt(const float* __restrict__ cb) {
    int i = blockIdx.x * 256 + threadIdx.x;          // over C_*N1
    if (i >= C_ * N1) return;
    int c = i / N1, v = i % N1;
    g_cbt16[i] = __float2half_rn(cb[(size_t)v * C_ + c]);
}

// -------- Softmax + argmax (+ exact fp64 rescue for narrow gaps) --------
// One warp per (bt, g) row of 160. Emits probs fp32 (output) + fp16 (GEMM2 input).
#define GAP_THRESH  0.015f
#define CAND_WINDOW 0.025f

__global__ void softmax_argmax_kernel(const float* __restrict__ gumbel,
                                      const float* __restrict__ x,
                                      const float* __restrict__ W,
                                      const float* __restrict__ bias,
                                      float* __restrict__ probs_out,
                                      float* __restrict__ codes_out)
{
    const int task = blockIdx.x * 8 + (threadIdx.x >> 5);   // 98304 tasks
    const int lane = threadIdx.x & 31;
    const int row = task >> 1, g = task & 1;

    const float* lp = g_logits + (size_t)row * N1 + g * VG_;
    const float* gp = gumbel   + (size_t)row * N1 + g * VG_;

    float z[5];
    float best = -INFINITY, second = -INFINITY;
    int bidx = 0;
    #pragma unroll
    for (int j = 0; j < 5; j++) {
        int v = lane + j * 32;
        z[j] = lp[v] + gp[v];
        if (z[j] > best) { second = best; best = z[j]; bidx = v; }
        else if (z[j] > second) { second = z[j]; }
    }
    #pragma unroll
    for (int o = 16; o > 0; o >>= 1) {
        float ov = __shfl_xor_sync(0xffffffffu, best,   o);
        float os = __shfl_xor_sync(0xffffffffu, second, o);
        int   oi = __shfl_xor_sync(0xffffffffu, bidx,   o);
        if (ov > best || (ov == best && oi < bidx)) {
            second = fmaxf(best, os);
            best = ov; bidx = oi;
        } else {
            second = fmaxf(second, ov);
        }
    }

    if (best - second < GAP_THRESH) {
        double nbest = -1e300;
        int nidx = 0;
        #pragma unroll
        for (int j = 0; j < 5; j++) {
            unsigned m = __ballot_sync(0xffffffffu, z[j] > best - CAND_WINDOW);
            while (m) {
                int l = __ffs(m) - 1; m &= m - 1;
                int v = l + j * 32;
                int col = g * VG_ + v;
                double part = 0.0;
                const float* xr = x + (size_t)row * C_;
                for (int k = lane; k < C_; k += 32)
                    part += (double)xr[k] * (double)W[(size_t)k * N1 + col];
                #pragma unroll
                for (int o = 16; o > 0; o >>= 1)
                    part += __shfl_xor_sync(0xffffffffu, part, o);
                double ze = part + (double)bias[col] + (double)gp[v];
                if (ze > nbest) { nbest = ze; nidx = v; }  // v strictly ascending -> first max kept
            }
        }
        bidx = nidx;
    }

    const float inv_t = 1.0f / TEMP_;
    float e[5];
    float s = 0.0f;
    #pragma unroll
    for (int j = 0; j < 5; j++) { e[j] = __expf((z[j] - best) * inv_t); s += e[j]; }
    #pragma unroll
    for (int o = 16; o > 0; o >>= 1) s += __shfl_xor_sync(0xffffffffu, s, o);
    float inv_s = 1.0f / s;

    float* po = probs_out + (size_t)row * N1 + g * VG_;
    __half* ph = g_probs16 + (size_t)row * N1 + g * VG_;
    #pragma unroll
    for (int j = 0; j < 5; j++) {
        int v = lane + j * 32;
        float p = e[j] * inv_s;
        po[v] = p;
        ph[v] = __float2half_rn(p);
    }

    if (lane == 0) codes_out[task] = (float)bidx;
}

// ---------------- launch ----------------
extern "C" void kernel_launch(void* const* d_in, const int* in_sizes, int n_in,
                              void* d_out, int out_size)
{
    const float* x      = (const float*)d_in[0];  // (B,T,C)
    const float* gumbel = (const float*)d_in[1];  // (B,T,G,Vg)
    const float* W      = (const float*)d_in[2];  // (C, G*Vg)
    const float* bias   = (const float*)d_in[3];  // (G*Vg,)
    const float* cb     = (const float*)d_in[4];  // (G,Vg,C) -> (320,768)

    float* out   = (float*)d_out;
    float* quant = out;                                      // M*C
    float* codes = out + (size_t)M_TOTAL * C_;               // M*G
    float* probs = codes + (size_t)M_TOTAL * G_;             // M*N1

    static float* logits_ptr = nullptr;
    static __half *wt16, *cbt16, *pr16;
    static bool init_done = false;
    if (!init_done) {
        cudaGetSymbolAddress((void**)&logits_ptr, g_logits);
        cudaGetSymbolAddress((void**)&wt16,  g_Wt16);
        cudaGetSymbolAddress((void**)&cbt16, g_cbt16);
        cudaGetSymbolAddress((void**)&pr16,  g_probs16);
        cudaFuncSetAttribute((const void*)gemm_f16_pipe<C_, N1, C_/BK, true, false>,
                             cudaFuncAttributeMaxDynamicSharedMemorySize, SMEM_G);
        cudaFuncSetAttribute((const void*)gemm_f16_pipe<N1, N2, N1/BK, false, true>,
                             cudaFuncAttributeMaxDynamicSharedMemorySize, SMEM_G);
        init_done = true;
    }

    // prep: W^T and cb^T fp16
    prep_Wt <<<(N1 * C_ + 255) / 256, 256>>>(W);
    prep_cbt<<<(C_ * N1 + 255) / 256, 256>>>(cb);

    // GEMM1: logits = x @ W + b   (M x 768) @ (768 x 320), fp16 MMA, fp32 acc
    gemm_f16_pipe<C_, N1, C_/BK, true, false>
        <<<dim3(N1 / 64, M_TOTAL / 128), 256, SMEM_G>>>(x, nullptr, wt16, bias, logits_ptr);

    // Softmax + argmax (+ exact rescue); emits probs fp32 + fp16
    softmax_argmax_kernel<<<(M_TOTAL * G_) / 8, 256>>>(gumbel, x, W, bias, probs, codes);

    // GEMM2: quantized = probs @ codebook   (M x 320) @ (320 x 768)
    gemm_f16_pipe<N1, N2, N1/BK, false, true>
        <<<dim3(N2 / 64, M_TOTAL / 128), 256, SMEM_G>>>(nullptr, pr16, cbt16, nullptr, quant);
}

// round 12
// speedup vs baseline: 2.5670x; 1.0460x over previous
#include <cuda_runtime.h>
#include <cuda_fp16.h>
#include <cstdint>
#include <math.h>

// Problem constants
#define B_  32
#define T_  1536
#define C_  768
#define G_  2
#define VG_ 160
#define M_TOTAL (B_*T_)       // 49152
#define N1 (G_*VG_)           // 320
#define N2 C_                 // 768
#define TEMP_ 2.0f

// GEMM tiling: BM=128, BN=64, BK=64 (fp16), 8 warps of 32x32
#define BK 64
#define P32 36                // b32 pitch per row (144B): conflict-free ldmatrix phases
#define SA (128*P32)          // A stage, b32 units (4608)
#define SB (64*P32)           // B stage, b32 units (2304)
#define SS (SA+SB)            // 6912
#define SMEM_G (2*SS*4)       // 55296 bytes

// ---- device scratch (allocation-free rule) ----
__device__ float   g_logits [(size_t)M_TOTAL * N1];
__device__ __half  g_probs16[(size_t)M_TOTAL * N1];
__device__ __half  g_Wt16   [(size_t)N1 * C_];   // [n][k]
__device__ __half  g_cbt16  [(size_t)C_ * N1];   // [c][v]

__device__ __forceinline__ void mma_f16(float c[4],
    uint32_t a0, uint32_t a1, uint32_t a2, uint32_t a3,
    uint32_t b0, uint32_t b1)
{
    asm volatile(
        "mma.sync.aligned.m16n8k16.row.col.f32.f16.f16.f32 "
        "{%0,%1,%2,%3}, {%4,%5,%6,%7}, {%8,%9}, {%0,%1,%2,%3};"
        : "+f"(c[0]), "+f"(c[1]), "+f"(c[2]), "+f"(c[3])
        : "r"(a0), "r"(a1), "r"(a2), "r"(a3), "r"(b0), "r"(b1));
}

__device__ __forceinline__ void ldsm4(uint32_t& r0, uint32_t& r1, uint32_t& r2, uint32_t& r3,
                                      uint32_t addr)
{
    asm volatile("ldmatrix.sync.aligned.m8n8.x4.shared.b16 {%0,%1,%2,%3}, [%4];"
                 : "=r"(r0), "=r"(r1), "=r"(r2), "=r"(r3) : "r"(addr));
}

__device__ __forceinline__ uint32_t s2u(const void* p){
    uint32_t a;
    asm("{ .reg .u64 t; cvta.to.shared.u64 t, %1; cvt.u32.u64 %0, t; }" : "=r"(a) : "l"(p));
    return a;
}

// D[M,N] = A[m][k] * B[n][k]^T ; A fp32 (converted inline) or fp16; B fp16 [n][k].
template<int KD, int ND, int NIT, bool HAS_BIAS, bool A_F16>
__global__ __launch_bounds__(256, 2)
void gemm_f16_pipe(const float* __restrict__ A32, const __half* __restrict__ A16,
                   const __half* __restrict__ Bg,
                   const float* __restrict__ bias, float* __restrict__ Out)
{
    extern __shared__ uint32_t sm32[];
    uint32_t* aS[2] = { sm32,       sm32 + SS };
    uint32_t* bS[2] = { sm32 + SA,  sm32 + SS + SA };
    const uint32_t smemB = s2u(sm32);
    const uint32_t aByte[2] = { smemB,             smemB + SS * 4 };
    const uint32_t bByte[2] = { smemB + SA * 4,    smemB + (SS + SA) * 4 };

    const int tid  = threadIdx.x;
    const int warp = tid >> 5, lane = tid & 31;
    const int wm = warp >> 1, wn = warp & 1;     // 4x2 warps -> 32x32 warp tiles
    const int m0 = blockIdx.y * 128, n0 = blockIdx.x * 64;
    const int g = lane >> 2, t = lane & 3;

    // ldmatrix per-lane offsets (byte), row pitch = 144B
    // A x4: m0: rows 0-7,k0-7 | m1: rows 8-15,k0-7 | m2: rows 0-7,k8-15 | m3: rows 8-15,k8-15
    const uint32_t aLane = (uint32_t)(lane & 15) * 144u + (uint32_t)(lane >> 4) * 16u;
    // B x4: m0: n0-7,k0-7 | m1: n0-7,k8-15 | m2: n8-15,k0-7 | m3: n8-15,k8-15
    const uint32_t bLane = (uint32_t)((lane & 7) | ((lane >> 4) << 3)) * 144u
                         + (uint32_t)((lane >> 3) & 1) * 16u;

    float acc[2][4][4];
    #pragma unroll
    for (int mt = 0; mt < 2; mt++)
        #pragma unroll
        for (int nt = 0; nt < 4; nt++)
            #pragma unroll
            for (int r = 0; r < 4; r++) acc[mt][nt][r] = 0.0f;

    // staging registers
    float4 avf[8];
    uint4  avh[4];
    uint4  bv[2];

    auto ldg = [&](int k0) {
        if (A_F16) {
            #pragma unroll
            for (int i = 0; i < 4; i++) {
                int idx = tid + i * 256, r = idx >> 3, ch = idx & 7;
                avh[i] = *(const uint4*)(A16 + (size_t)(m0 + r) * KD + k0 + ch * 8);
            }
        } else {
            #pragma unroll
            for (int i = 0; i < 8; i++) {
                int idx = tid + i * 256, r = idx >> 4, c4 = idx & 15;
                avf[i] = *(const float4*)(A32 + (size_t)(m0 + r) * KD + k0 + c4 * 4);
            }
        }
        #pragma unroll
        for (int i = 0; i < 2; i++) {
            int idx = tid + i * 256, r = idx >> 3, ch = idx & 7;
            bv[i] = *(const uint4*)(Bg + (size_t)(n0 + r) * KD + k0 + ch * 8);
        }
    };

    auto sts = [&](int s) {
        uint32_t* aD = aS[s];
        uint32_t* bD = bS[s];
        if (A_F16) {
            #pragma unroll
            for (int i = 0; i < 4; i++) {
                int idx = tid + i * 256, r = idx >> 3, ch = idx & 7;
                *(uint4*)(aD + r * P32 + ch * 4) = avh[i];
            }
        } else {
            #pragma unroll
            for (int i = 0; i < 8; i++) {
                int idx = tid + i * 256, r = idx >> 4, c4 = idx & 15;
                __half2 h01 = __floats2half2_rn(avf[i].x, avf[i].y);  // x -> low half (even k)
                __half2 h23 = __floats2half2_rn(avf[i].z, avf[i].w);
                *(uint2*)(aD + r * P32 + c4 * 2) =
                    make_uint2(*(uint32_t*)&h01, *(uint32_t*)&h23);
            }
        }
        #pragma unroll
        for (int i = 0; i < 2; i++) {
            int idx = tid + i * 256, r = idx >> 3, ch = idx & 7;
            *(uint4*)(bD + r * P32 + ch * 4) = bv[i];
        }
    };

    ldg(0);
    #pragma unroll 1
    for (int it = 0; it < NIT; ++it) {
        sts(it & 1);
        if (it + 1 < NIT) ldg((it + 1) * BK);
        __syncthreads();

        const uint32_t aBase = aByte[it & 1] + (uint32_t)(wm * 32) * 144u + aLane;
        const uint32_t bBase = bByte[it & 1] + (uint32_t)(wn * 32) * 144u + bLane;
        #pragma unroll
        for (int ks = 0; ks < 4; ks++) {
            const uint32_t kOff = (uint32_t)ks * 32u;   // 16 halfs = 32B
            uint32_t a[2][4];
            ldsm4(a[0][0], a[0][1], a[0][2], a[0][3], aBase + kOff);
            ldsm4(a[1][0], a[1][1], a[1][2], a[1][3], aBase + 16u * 144u + kOff);
            #pragma unroll
            for (int p = 0; p < 2; p++) {
                uint32_t b00, b01, b10, b11;   // (n-tile p*2: b0,b1), (n-tile p*2+1: b0,b1)
                ldsm4(b00, b01, b10, b11, bBase + (uint32_t)(p * 16) * 144u + kOff);
                mma_f16(acc[0][p*2  ], a[0][0], a[0][1], a[0][2], a[0][3], b00, b01);
                mma_f16(acc[1][p*2  ], a[1][0], a[1][1], a[1][2], a[1][3], b00, b01);
                mma_f16(acc[0][p*2+1], a[0][0], a[0][1], a[0][2], a[0][3], b10, b11);
                mma_f16(acc[1][p*2+1], a[1][0], a[1][1], a[1][2], a[1][3], b10, b11);
            }
        }
    }

    // Epilogue (float2 stores)
    #pragma unroll
    for (int mt = 0; mt < 2; mt++) {
        #pragma unroll
        for (int nt = 0; nt < 4; nt++) {
            int row0 = m0 + wm * 32 + mt * 16 + g;
            int col0 = n0 + wn * 32 + nt * 8 + t * 2;
            float2 v01 = make_float2(acc[mt][nt][0], acc[mt][nt][1]);
            float2 v23 = make_float2(acc[mt][nt][2], acc[mt][nt][3]);
            if (HAS_BIAS) {
                float bv0 = bias[col0], bv1 = bias[col0 + 1];
                v01.x += bv0; v01.y += bv1;
                v23.x += bv0; v23.y += bv1;
            }
            *(float2*)(Out + (size_t)(row0    ) * ND + col0) = v01;
            *(float2*)(Out + (size_t)(row0 + 8) * ND + col0) = v23;
        }
    }
}

// ---------------- prep: transpose + fp16 convert of W and codebook ----------------
__global__ void prep_Wt(const float* __restrict__ W) {
    int i = blockIdx.x * 256 + threadIdx.x;          // over N1*C_
    if (i >= N1 * C_) return;
    int n = i / C_, k = i % C_;
    g_Wt16[i] = __float2half_rn(W[(size_t)k * N1 + n]);
}
__global__ void prep_cbt(const float* __restrict__ cb) {
    int i = blockIdx.x * 256 + threadIdx.x;          // over C_*N1
    if (i >= C_ * N1) return;
    int c = i / N1, v = i % N1;
    g_cbt16[i] = __float2half_rn(cb[(size_t)v * C_ + c]);
}

// -------- Softmax + argmax (+ exact fp64 rescue for narrow gaps) --------
// One warp per (bt, g) row of 160. Emits probs fp32 (output) + fp16 (GEMM2 input).
#define GAP_THRESH  0.015f
#define CAND_WINDOW 0.025f

__global__ void softmax_argmax_kernel(const float* __restrict__ gumbel,
                                      const float* __restrict__ x,
                                      const float* __restrict__ W,
                                      const float* __restrict__ bias,
                                      float* __restrict__ probs_out,
                                      float* __restrict__ codes_out)
{
    const int task = blockIdx.x * 8 + (threadIdx.x >> 5);   // 98304 tasks
    const int lane = threadIdx.x & 31;
    const int row = task >> 1, g = task & 1;

    const float* lp = g_logits + (size_t)row * N1 + g * VG_;
    const float* gp = gumbel   + (size_t)row * N1 + g * VG_;

    float z[5];
    float best = -INFINITY, second = -INFINITY;
    int bidx = 0;
    #pragma unroll
    for (int j = 0; j < 5; j++) {
        int v = lane + j * 32;
        z[j] = lp[v] + gp[v];
        if (z[j] > best) { second = best; best = z[j]; bidx = v; }
        else if (z[j] > second) { second = z[j]; }
    }
    #pragma unroll
    for (int o = 16; o > 0; o >>= 1) {
        float ov = __shfl_xor_sync(0xffffffffu, best,   o);
        float os = __shfl_xor_sync(0xffffffffu, second, o);
        int   oi = __shfl_xor_sync(0xffffffffu, bidx,   o);
        if (ov > best || (ov == best && oi < bidx)) {
            second = fmaxf(best, os);
            best = ov; bidx = oi;
        } else {
            second = fmaxf(second, ov);
        }
    }

    if (best - second < GAP_THRESH) {
        double nbest = -1e300;
        int nidx = 0;
        #pragma unroll
        for (int j = 0; j < 5; j++) {
            unsigned m = __ballot_sync(0xffffffffu, z[j] > best - CAND_WINDOW);
            while (m) {
                int l = __ffs(m) - 1; m &= m - 1;
                int v = l + j * 32;
                int col = g * VG_ + v;
                double part = 0.0;
                const float* xr = x + (size_t)row * C_;
                for (int k = lane; k < C_; k += 32)
                    part += (double)xr[k] * (double)W[(size_t)k * N1 + col];
                #pragma unroll
                for (int o = 16; o > 0; o >>= 1)
                    part += __shfl_xor_sync(0xffffffffu, part, o);
                double ze = part + (double)bias[col] + (double)gp[v];
                if (ze > nbest) { nbest = ze; nidx = v; }  // v strictly ascending -> first max kept
            }
        }
        bidx = nidx;
    }

    const float inv_t = 1.0f / TEMP_;
    float e[5];
    float s = 0.0f;
    #pragma unroll
    for (int j = 0; j < 5; j++) { e[j] = __expf((z[j] - best) * inv_t); s += e[j]; }
    #pragma unroll
    for (int o = 16; o > 0; o >>= 1) s += __shfl_xor_sync(0xffffffffu, s, o);
    float inv_s = 1.0f / s;

    float* po = probs_out + (size_t)row * N1 + g * VG_;
    __half* ph = g_probs16 + (size_t)row * N1 + g * VG_;
    #pragma unroll
    for (int j = 0; j < 5; j++) {
        int v = lane + j * 32;
        float p = e[j] * inv_s;
        po[v] = p;
        ph[v] = __float2half_rn(p);
    }

    if (lane == 0) codes_out[task] = (float)bidx;
}

// ---------------- launch ----------------
extern "C" void kernel_launch(void* const* d_in, const int* in_sizes, int n_in,
                              void* d_out, int out_size)
{
    const float* x      = (const float*)d_in[0];  // (B,T,C)
    const float* gumbel = (const float*)d_in[1];  // (B,T,G,Vg)
    const float* W      = (const float*)d_in[2];  // (C, G*Vg)
    const float* bias   = (const float*)d_in[3];  // (G*Vg,)
    const float* cb     = (const float*)d_in[4];  // (G,Vg,C) -> (320,768)

    float* out   = (float*)d_out;
    float* quant = out;                                      // M*C
    float* codes = out + (size_t)M_TOTAL * C_;               // M*G
    float* probs = codes + (size_t)M_TOTAL * G_;             // M*N1

    static float* logits_ptr = nullptr;
    static __half *wt16, *cbt16, *pr16;
    static bool init_done = false;
    if (!init_done) {
        cudaGetSymbolAddress((void**)&logits_ptr, g_logits);
        cudaGetSymbolAddress((void**)&wt16,  g_Wt16);
        cudaGetSymbolAddress((void**)&cbt16, g_cbt16);
        cudaGetSymbolAddress((void**)&pr16,  g_probs16);
        cudaFuncSetAttribute((const void*)gemm_f16_pipe<C_, N1, C_/BK, true, false>,
                             cudaFuncAttributeMaxDynamicSharedMemorySize, SMEM_G);
        cudaFuncSetAttribute((const void*)gemm_f16_pipe<N1, N2, N1/BK, false, true>,
                             cudaFuncAttributeMaxDynamicSharedMemorySize, SMEM_G);
        init_done = true;
    }

    // prep: W^T and cb^T fp16
    prep_Wt <<<(N1 * C_ + 255) / 256, 256>>>(W);
    prep_cbt<<<(C_ * N1 + 255) / 256, 256>>>(cb);

    // GEMM1: logits = x @ W + b   (M x 768) @ (768 x 320), fp16 MMA, fp32 acc
    gemm_f16_pipe<C_, N1, C_/BK, true, false>
        <<<dim3(N1 / 64, M_TOTAL / 128), 256, SMEM_G>>>(x, nullptr, wt16, bias, logits_ptr);

    // Softmax + argmax (+ exact rescue); emits probs fp32 + fp16
    softmax_argmax_kernel<<<(M_TOTAL * G_) / 8, 256>>>(gumbel, x, W, bias, probs, codes);

    // GEMM2: quantized = probs @ codebook   (M x 320) @ (320 x 768)
    gemm_f16_pipe<N1, N2, N1/BK, false, true>
        <<<dim3(N2 / 64, M_TOTAL / 128), 256, SMEM_G>>>(nullptr, pr16, cbt16, nullptr, quant);
}